// round 1
// baseline (speedup 1.0000x reference)
#include <cuda_runtime.h>
#include <cstdint>

#define M_NODES 100000
#define DD      128
#define E_EDGES 1600000
#define KTOT    384
#define NGRAPH  16

// ---------------- device scratch (static: allocation-free) ----------------
__device__ __align__(16) float g_sum[(size_t)M_NODES * DD]; // 51.2 MB edge sums
__device__ float g_cnt[M_NODES];
__device__ int   g_is64; // 1 if index tensors are int64, 0 if int32

// ---------------- f32x2 packed-math helpers (full-rate fp32 on sm_103a) ----
__device__ __forceinline__ unsigned long long splat2(float x) {
    unsigned long long r;
    asm("mov.b64 %0, {%1, %1};" : "=l"(r) : "f"(x));
    return r;
}
__device__ __forceinline__ unsigned long long fma2(unsigned long long a,
                                                   unsigned long long b,
                                                   unsigned long long c) {
    unsigned long long d;
    asm("fma.rn.f32x2 %0, %1, %2, %3;" : "=l"(d) : "l"(a), "l"(b), "l"(c));
    return d;
}
__device__ __forceinline__ float2 unpack2(unsigned long long v) {
    float2 r;
    asm("mov.b64 {%0, %1}, %2;" : "=f"(r.x), "=f"(r.y) : "l"(v));
    return r;
}

// ---------------- kernel 0: zero the accumulators --------------------------
__global__ void zero_kernel() {
    const int stride = gridDim.x * blockDim.x;
    int t = blockIdx.x * blockDim.x + threadIdx.x;
    const long long n = (long long)M_NODES * DD;
    for (long long i = t; i < n; i += stride) g_sum[i] = 0.0f;
    for (int i = t; i < M_NODES; i += stride) g_cnt[i] = 0.0f;
}

// ---------------- kernel 0b: detect int64 vs int32 index dtype -------------
// If edge_index is int64 (values < 2^32), every odd uint32 word is 0.
// If it is int32, odd words are random node indices -> OR is nonzero.
__global__ void detect_kernel(const unsigned int* ei_words) {
    __shared__ unsigned int s;
    if (threadIdx.x == 0) s = 0u;
    __syncthreads();
    unsigned int v = 0u;
    for (int i = threadIdx.x; i < 8192; i += blockDim.x) v |= ei_words[2 * i + 1];
    atomicOr(&s, v);
    __syncthreads();
    if (threadIdx.x == 0) g_is64 = (s == 0u) ? 1 : 0;
}

// ---------------- kernel 1: scatter-add edges (one warp per edge) ----------
__global__ void scatter_kernel(const float* __restrict__ edge_attr,
                               const void* __restrict__ edge_index) {
    const int lane   = threadIdx.x & 31;
    const int warp   = (blockIdx.x * blockDim.x + threadIdx.x) >> 5;
    const int nwarps = (gridDim.x * blockDim.x) >> 5;
    const int is64   = g_is64;
    const long long* ei64 = (const long long*)edge_index;
    const int*       ei32 = (const int*)edge_index;

    for (int e = warp; e < E_EDGES; e += nwarps) {
        int dest = 0;
        if (lane == 0)
            dest = is64 ? (int)ei64[(long long)E_EDGES + e] : ei32[E_EDGES + e];
        dest = __shfl_sync(0xffffffffu, dest, 0);

        float4 v = *(const float4*)(edge_attr + (long long)e * DD + lane * 4);
        float* p = g_sum + (long long)dest * DD + lane * 4;
        asm volatile("red.global.add.v4.f32 [%0], {%1, %2, %3, %4};"
                     :: "l"(p), "f"(v.x), "f"(v.y), "f"(v.z), "f"(v.w)
                     : "memory");
        if (lane == 0) atomicAdd(&g_cnt[dest], 1.0f);
    }
}

// ---------------- kernel 2: fused concat + MLP (both GEMMs) ----------------
// Block computes 128 rows x all 128 output cols.
// Phase A: H = relu(feats @ W1 + b1), feats built on the fly from x / agg / u.
// Phase B: out = H @ W2 + b2 (W2 staged in SMEM, H lives in SMEM).
#define BM 128
#define BN 128
#define BK 16
#define HS_STRIDE 132   // padded row stride for Hs

// dynamic smem layout (floats):
//   As  [BK][BM]       : 2048
//   Bs  [BK][BN]       : 2048
//   W2s [128][128]     : 16384
//   Hs  [BM][HS_STRIDE]: 16896
#define SMEM_FLOATS (2048 + 2048 + 16384 + 16896)

extern __shared__ float smem_f[];

__global__ __launch_bounds__(256, 1)
void fused_mlp_kernel(const float* __restrict__ x,
                      const float* __restrict__ u,
                      const float* __restrict__ W1,
                      const float* __restrict__ b1,
                      const float* __restrict__ W2,
                      const float* __restrict__ b2,
                      const void*  __restrict__ batch_ptr,
                      float* __restrict__ out) {
    float* As  = smem_f;                 // transposed: As[kk*BM + m]
    float* Bs  = smem_f + 2048;          // Bs[kk*BN + n]
    float* W2s = smem_f + 4096;          // W2s[k*128 + n]
    float* Hs  = smem_f + 4096 + 16384;  // Hs[m*HS_STRIDE + k]

    const int tid  = threadIdx.x;
    const int tx   = tid & 15;           // output col group
    const int ty   = tid >> 4;           // output row group
    const int row0 = ty * 8;
    const int col0 = tx * 8;
    const int gm0  = blockIdx.x * BM;

    const int is64 = g_is64;
    const long long* bat64 = (const long long*)batch_ptr;
    const int*       bat32 = (const int*)batch_ptr;

    // stage W2 (needed only in phase B; syncs before use are implied by loop syncs)
    #pragma unroll
    for (int i = 0; i < 16; i++)
        ((float4*)W2s)[tid + i * 256] = ((const float4*)W2)[tid + i * 256];

    unsigned long long acc[8][4];
    #pragma unroll
    for (int i = 0; i < 8; i++)
        #pragma unroll
        for (int j = 0; j < 4; j++) acc[i][j] = 0ull;

    // ---------------- Phase A: H = relu(feats @ W1 + b1) ----------------
    for (int t = 0; t < KTOT / BK; t++) {
        const int kbase = t * BK;
        // A tile: 128 rows x 16 k, built from the three feature sources
        #pragma unroll
        for (int i = 0; i < 2; i++) {
            int idx = tid + i * 256;
            int r = idx >> 2;
            int q = idx & 3;
            int m = gm0 + r;
            int k = kbase + q * 4;
            float4 v = make_float4(0.f, 0.f, 0.f, 0.f);
            if (m < M_NODES) {
                if (k < 128) {
                    v = *(const float4*)(x + (long long)m * DD + k);
                } else if (k < 256) {
                    v = *(const float4*)(g_sum + (long long)m * DD + (k - 128));
                    float inv = 1.0f / fmaxf(g_cnt[m], 1.0f);
                    v.x *= inv; v.y *= inv; v.z *= inv; v.w *= inv;
                } else {
                    long long b = is64 ? bat64[m] : (long long)bat32[m];
                    v = *(const float4*)(u + b * DD + (k - 256));
                }
            }
            int kk = q * 4;
            As[(kk + 0) * BM + r] = v.x;
            As[(kk + 1) * BM + r] = v.y;
            As[(kk + 2) * BM + r] = v.z;
            As[(kk + 3) * BM + r] = v.w;
        }
        // B tile: W1[kbase .. kbase+15][0..127]
        #pragma unroll
        for (int i = 0; i < 2; i++) {
            int idx = tid + i * 256;
            int r = idx >> 5;
            int q = idx & 31;
            ((float4*)(Bs + r * BN))[q] =
                ((const float4*)(W1 + (long long)(kbase + r) * DD))[q];
        }
        __syncthreads();

        #pragma unroll
        for (int kk = 0; kk < BK; kk++) {
            float4 a0 = *(const float4*)(As + kk * BM + row0);
            float4 a1 = *(const float4*)(As + kk * BM + row0 + 4);
            float a[8] = {a0.x, a0.y, a0.z, a0.w, a1.x, a1.y, a1.z, a1.w};
            const ulonglong2* bp = (const ulonglong2*)(Bs + kk * BN + col0);
            ulonglong2 bA = bp[0], bB = bp[1];
            unsigned long long bv[4] = {bA.x, bA.y, bB.x, bB.y};
            #pragma unroll
            for (int i = 0; i < 8; i++) {
                unsigned long long ai = splat2(a[i]);
                #pragma unroll
                for (int j = 0; j < 4; j++) acc[i][j] = fma2(ai, bv[j], acc[i][j]);
            }
        }
        __syncthreads();
    }

    // bias + relu, park H in SMEM
    float b1v[8];
    #pragma unroll
    for (int j = 0; j < 8; j++) b1v[j] = b1[col0 + j];
    #pragma unroll
    for (int i = 0; i < 8; i++) {
        #pragma unroll
        for (int jp = 0; jp < 4; jp++) {
            float2 p = unpack2(acc[i][jp]);
            float h0 = fmaxf(p.x + b1v[2 * jp], 0.0f);
            float h1 = fmaxf(p.y + b1v[2 * jp + 1], 0.0f);
            *(float2*)(Hs + (row0 + i) * HS_STRIDE + col0 + 2 * jp) =
                make_float2(h0, h1);
        }
    }
    __syncthreads();

    // ---------------- Phase B: out = H @ W2 + b2 ----------------
    #pragma unroll
    for (int i = 0; i < 8; i++)
        #pragma unroll
        for (int j = 0; j < 4; j++) acc[i][j] = 0ull;

    #pragma unroll 4
    for (int kk = 0; kk < 128; kk++) {
        const ulonglong2* bp = (const ulonglong2*)(W2s + kk * 128 + col0);
        ulonglong2 bA = bp[0], bB = bp[1];
        unsigned long long bv[4] = {bA.x, bA.y, bB.x, bB.y};
        #pragma unroll
        for (int i = 0; i < 8; i++) {
            unsigned long long ai = splat2(Hs[(row0 + i) * HS_STRIDE + kk]);
            #pragma unroll
            for (int j = 0; j < 4; j++) acc[i][j] = fma2(ai, bv[j], acc[i][j]);
        }
    }

    float b2v[8];
    #pragma unroll
    for (int j = 0; j < 8; j++) b2v[j] = b2[col0 + j];
    #pragma unroll
    for (int i = 0; i < 8; i++) {
        int m = gm0 + row0 + i;
        if (m < M_NODES) {
            float2 p0 = unpack2(acc[i][0]);
            float2 p1 = unpack2(acc[i][1]);
            float2 p2 = unpack2(acc[i][2]);
            float2 p3 = unpack2(acc[i][3]);
            float4 o0 = make_float4(p0.x + b2v[0], p0.y + b2v[1],
                                    p1.x + b2v[2], p1.y + b2v[3]);
            float4 o1 = make_float4(p2.x + b2v[4], p2.y + b2v[5],
                                    p3.x + b2v[6], p3.y + b2v[7]);
            *(float4*)(out + (long long)m * DD + col0)     = o0;
            *(float4*)(out + (long long)m * DD + col0 + 4) = o1;
        }
    }
}

// ---------------- host launcher --------------------------------------------
extern "C" void kernel_launch(void* const* d_in, const int* in_sizes, int n_in,
                              void* d_out, int out_size) {
    const float* x         = (const float*)d_in[0];
    const float* edge_attr = (const float*)d_in[1];
    const float* u         = (const float*)d_in[2];
    const float* W1        = (const float*)d_in[3];
    const float* b1        = (const float*)d_in[4];
    const float* W2        = (const float*)d_in[5];
    const float* b2        = (const float*)d_in[6];
    const void*  edge_index = d_in[7];
    const void*  batch      = d_in[8];
    float* out = (float*)d_out;

    static bool attr_set = false;
    if (!attr_set) {
        cudaFuncSetAttribute(fused_mlp_kernel,
                             cudaFuncAttributeMaxDynamicSharedMemorySize,
                             SMEM_FLOATS * sizeof(float));
        attr_set = true;
    }

    zero_kernel<<<2048, 256>>>();
    detect_kernel<<<1, 256>>>((const unsigned int*)edge_index);
    scatter_kernel<<<1184, 256>>>(edge_attr, edge_index);

    int nblocks = (M_NODES + BM - 1) / BM;  // 782
    fused_mlp_kernel<<<nblocks, 256, SMEM_FLOATS * sizeof(float)>>>(
        x, u, W1, b1, W2, b2, batch, out);
}